// round 7
// baseline (speedup 1.0000x reference)
#include <cuda_runtime.h>
#include <cuda_bf16.h>

// Problem constants (fixed shapes from reference)
#define NB     64
#define CC     256
#define EMB    16
#define HW     3136                 // 56*56
#define IDX    16                   // ceil(256^(0.5))
#define SCALEF (256.0f / 240.0f)    // c / (c - INDEX)

#define TOTAL4  ((unsigned)NB * CC * HW / 4)   // 12,845,056 float4
#define SLAB4   (HW / 4)                       // 784 float4 per (n,c) slab
#define ITERS   8u
#define STRIDE4 (TOTAL4 / ITERS)               // 1,605,632

// Per-(n,c) multiplier: SCALEF if channel kept, 0 if dropped.
__device__ float g_mult[NB * CC];

// ---------------------------------------------------------------------------
// Kernel 1: one block per sample row n. Compute activ[n][c] = embeds[n]·table[:,c],
// find the value at sorted index IDX (17th smallest) via rank counting, and
// emit the per-channel multiplier.
// ---------------------------------------------------------------------------
__global__ void drop_thresh_kernel(const float* __restrict__ embeds,
                                   const float* __restrict__ table) {
    __shared__ float s_emb[EMB];
    __shared__ float s_act[CC];
    __shared__ float s_thr;

    const int n = blockIdx.x;
    const int c = threadIdx.x;

    if (c < EMB) s_emb[c] = embeds[n * EMB + c];
    __syncthreads();

    float a = 0.0f;
#pragma unroll
    for (int e = 0; e < EMB; e++)
        a = fmaf(s_emb[e], table[e * CC + c], a);   // coalesced across c
    s_act[c] = a;
    __syncthreads();

    // Rank of this thread's value among the 256 row values.
    int less = 0, leq = 0;
#pragma unroll 8
    for (int j = 0; j < CC; j++) {
        const float v = s_act[j];
        less += (v <  a);
        leq  += (v <= a);
    }
    // Sorted-index-IDX element: #{< v} <= IDX and #{<= v} > IDX.
    // (Tie-correct: all tied holders write the same value.)
    if (less <= IDX && leq > IDX) s_thr = a;
    __syncthreads();

    g_mult[n * CC + c] = (s_thr <= a) ? SCALEF : 0.0f;
}

// ---------------------------------------------------------------------------
// Kernel 2: pure HBM stream. out = x * mult[slab].
// Branch-free: unconditional load+multiply (x finite => x*0 == 0 exactly),
// fixed 8-trip fully-unrolled loop so ptxas front-batches 8 independent
// LDG.128s (MLP_p1=8). Grid*threads*8 == TOTAL4 exactly — no tail predicate.
// Touch-once data on both sides: cache-streaming loads/stores.
// ---------------------------------------------------------------------------
__global__ void __launch_bounds__(256)
drop_apply_kernel(const float4* __restrict__ x, float4* __restrict__ out) {
    const unsigned tid = blockIdx.x * 256u + threadIdx.x;
#pragma unroll
    for (unsigned k = 0; k < ITERS; k++) {
        const unsigned i = tid + k * STRIDE4;
        const float m = g_mult[i / SLAB4];    // 16 KB table, L1-resident
        float4 v = __ldcs(&x[i]);
        v.x *= m; v.y *= m; v.z *= m; v.w *= m;
        __stcs(&out[i], v);
    }
}

extern "C" void kernel_launch(void* const* d_in, const int* in_sizes, int n_in,
                              void* d_out, int out_size) {
    const float* x      = (const float*)d_in[0];   // [64,256,56,56]
    const float* embeds = (const float*)d_in[1];   // [64,16]
    const float* table  = (const float*)d_in[2];   // [16,256]
    float* out = (float*)d_out;

    drop_thresh_kernel<<<NB, CC>>>(embeds, table);

    // 6272 blocks * 256 threads * 8 iters == TOTAL4 exactly.
    drop_apply_kernel<<<STRIDE4 / 256, 256>>>((const float4*)x, (float4*)out);
}